// round 15
// baseline (speedup 1.0000x reference)
#include <cuda_runtime.h>
#include <cuda_bf16.h>
#include <cstdint>

#define N_NODES 100000
#define IN_F    512
#define HID     128
#define NCLS    32
#define E_MAX   1600000
#define NB_SCAN 98          // ceil(100000/1024)

// ---------------- scratch (static device globals; no allocations) ----------
__device__ __align__(16) float g_dinv[N_NODES];
__device__ __align__(16) float g_h  [(size_t)N_NODES * HID];   // raw h (x @ W1)
__device__ __align__(16) float g_h2 [(size_t)N_NODES * NCLS];  // h2*dinv
// W1^T packed bf16x2: [n][kpair]
__device__ __align__(16) uint32_t g_w1t_hi[(size_t)HID * (IN_F / 2)];
__device__ __align__(16) uint32_t g_w1t_lo[(size_t)HID * (IN_F / 2)];
// CSR
__device__ int g_deg[N_NODES];
__device__ int g_rowptr[N_NODES + 1];
__device__ int g_bsums[NB_SCAN];
__device__ int g_tops[NB_SCAN];
__device__ int g_fill[N_NODES];
__device__ int g_adj[E_MAX];

// ---------------- helpers ---------------------------------------------------
__device__ __forceinline__ uint32_t smem_u32(const void* p) {
    uint32_t a;
    asm("{ .reg .u64 t; cvta.to.shared.u64 t, %1; cvt.u32.u64 %0, t; }"
        : "=r"(a) : "l"(p));
    return a;
}

__device__ __forceinline__ void ldsm_x4(uint32_t* r, uint32_t addr) {
    asm volatile("ldmatrix.sync.aligned.m8n8.x4.shared.b16 {%0,%1,%2,%3}, [%4];"
        : "=r"(r[0]), "=r"(r[1]), "=r"(r[2]), "=r"(r[3]) : "r"(addr));
}
__device__ __forceinline__ void ldsm_x2(uint32_t* r, uint32_t addr) {
    asm volatile("ldmatrix.sync.aligned.m8n8.x2.shared.b16 {%0,%1}, [%2];"
        : "=r"(r[0]), "=r"(r[1]) : "r"(addr));
}

__device__ __forceinline__ void mma_bf16(float* d, const uint32_t* a, const uint32_t* b) {
    asm volatile(
        "mma.sync.aligned.m16n8k16.row.col.f32.bf16.bf16.f32 "
        "{%0,%1,%2,%3}, {%4,%5,%6,%7}, {%8,%9}, {%0,%1,%2,%3};"
        : "+f"(d[0]), "+f"(d[1]), "+f"(d[2]), "+f"(d[3])
        : "r"(a[0]), "r"(a[1]), "r"(a[2]), "r"(a[3]), "r"(b[0]), "r"(b[1]));
}

__device__ __forceinline__ uint32_t pack_bf2(__nv_bfloat16 a, __nv_bfloat16 b) {
    return (uint32_t)__bfloat16_as_ushort(a) |
           ((uint32_t)__bfloat16_as_ushort(b) << 16);
}

// packed hi/lo split: ph = (bf16(vb)<<16)|bf16(va), pl = residuals likewise
__device__ __forceinline__ void split_pair(float va, float vb,
                                           uint32_t& ph, uint32_t& pl) {
    asm("cvt.rn.bf16x2.f32 %0, %1, %2;" : "=r"(ph) : "f"(vb), "f"(va));
    float h0 = __uint_as_float(ph << 16);
    float h1 = __uint_as_float(ph & 0xFFFF0000u);
    float l0 = va - h0;
    float l1 = vb - h1;
    asm("cvt.rn.bf16x2.f32 %0, %1, %2;" : "=r"(pl) : "f"(l1), "f"(l0));
}

// ---------------- degree / CSR build ---------------------------------------
__global__ void k_deg_zero() {
    int i = blockIdx.x * blockDim.x + threadIdx.x;
    if (i < N_NODES) g_deg[i] = 0;
}
__global__ void k_deg_count(const int* __restrict__ dst, int E) {
    int e = blockIdx.x * blockDim.x + threadIdx.x;
    if (e < E) atomicAdd(&g_deg[dst[e]], 1);
}
__global__ __launch_bounds__(1024) void k_scan_block() {
    __shared__ int s[1024];
    int tid = threadIdx.x;
    int i = blockIdx.x * 1024 + tid;
    int v = (i < N_NODES) ? g_deg[i] : 0;
    s[tid] = v;
    __syncthreads();
    #pragma unroll
    for (int off = 1; off < 1024; off <<= 1) {
        int t = (tid >= off) ? s[tid - off] : 0;
        __syncthreads();
        s[tid] += t;
        __syncthreads();
    }
    if (i < N_NODES) g_rowptr[i] = s[tid] - v;
    if (tid == 1023) g_bsums[blockIdx.x] = s[1023];
}
__global__ __launch_bounds__(128) void k_scan_tops() {
    __shared__ int s[128];
    int t = threadIdx.x;
    int v = (t < NB_SCAN) ? g_bsums[t] : 0;
    s[t] = v;
    __syncthreads();
    #pragma unroll
    for (int off = 1; off < 128; off <<= 1) {
        int u = (t >= off) ? s[t - off] : 0;
        __syncthreads();
        s[t] += u;
        __syncthreads();
    }
    if (t < NB_SCAN) g_tops[t] = s[t] - v;   // exclusive
}
__global__ __launch_bounds__(1024) void k_scan_add(int E) {
    int i = blockIdx.x * 1024 + threadIdx.x;
    if (i < N_NODES) {
        g_rowptr[i] += g_tops[blockIdx.x];
        g_fill[i] = 0;
        g_dinv[i] = rsqrtf((float)(g_deg[i] + 1));
    }
    if (i == 0) g_rowptr[N_NODES] = E;
}
__global__ void k_fill(const int* __restrict__ src, const int* __restrict__ dst, int E) {
    int e = blockIdx.x * blockDim.x + threadIdx.x;
    if (e >= E) return;
    int d = dst[e];
    int pos = atomicAdd(&g_fill[d], 1);
    g_adj[g_rowptr[d] + pos] = src[e];
}

// ---------------- W1 transpose + bf16 hi/lo split --------------------------
__global__ void k_w1t(const float* __restrict__ W1) {
    int idx = blockIdx.x * blockDim.x + threadIdx.x;
    if (idx >= HID * (IN_F / 2)) return;
    int n  = idx >> 8;
    int kp = idx & 255;
    float v0 = W1[(size_t)(2 * kp)     * HID + n];
    float v1 = W1[(size_t)(2 * kp + 1) * HID + n];
    __nv_bfloat16 h0 = __float2bfloat16_rn(v0);
    __nv_bfloat16 h1 = __float2bfloat16_rn(v1);
    __nv_bfloat16 l0 = __float2bfloat16_rn(v0 - __bfloat162float(h0));
    __nv_bfloat16 l1 = __float2bfloat16_rn(v1 - __bfloat162float(h1));
    g_w1t_hi[idx] = pack_bf2(h0, h1);
    g_w1t_lo[idx] = pack_bf2(l0, l1);
}

// ---------------- GEMM1 (bf16 mma m16n8k16, 3-term split, ldmatrix) --------
// writes RAW h (no dinv) -> no dependency on CSR chain
#define ASTR 20
#define NIT  (IN_F / 32)
#define OFF_AHI 0
#define OFF_ALO 2560
#define OFF_BHI 5120
#define OFF_BLO 7680
#define BUF_U32 10240
#define SMEM_BYTES (2 * BUF_U32 * 4)   // 81920

__global__ __launch_bounds__(256, 2) void k_gemm1(const float* __restrict__ A) {
    extern __shared__ __align__(16) uint32_t sm[];
    const uint32_t sbase = smem_u32(sm);

    const int tid  = threadIdx.x;
    const int wid  = tid >> 5;
    const int lane = tid & 31;
    const int gid  = lane >> 2;
    const int tig  = lane & 3;
    const int wm   = wid >> 2;
    const int wn   = wid & 3;
    const int row0 = blockIdx.x * 128;

    const int st_r  = tid >> 1;
    const int st_kp = (tid & 1) * 8;

    const int lm_a_row = lane & 15;
    const int lm_a_kb  = ((lane >> 4) & 1) * 4;
    const int lm_b_row = lane & 7;
    const int lm_b_kb  = ((lane >> 3) & 1) * 4;

    float acc[4][4][4];
    #pragma unroll
    for (int i = 0; i < 4; i++)
        #pragma unroll
        for (int j = 0; j < 4; j++)
            #pragma unroll
            for (int v = 0; v < 4; v++) acc[i][j][v] = 0.0f;

    const bool a_valid = (row0 + st_r) < N_NODES;
    const float* a_ptr = A + (size_t)(row0 + st_r) * IN_F + st_kp * 2;
    const uint32_t* bhi_ptr = g_w1t_hi + (size_t)st_r * (IN_F / 2) + st_kp;
    const uint32_t* blo_ptr = g_w1t_lo + (size_t)st_r * (IN_F / 2) + st_kp;

    float4 ar[4];
    uint4  bhr[2], blr[2];

    #pragma unroll
    for (int q = 0; q < 4; q++)
        ar[q] = a_valid ? *(const float4*)(a_ptr + q * 4)
                        : make_float4(0.f, 0.f, 0.f, 0.f);
    bhr[0] = *(const uint4*)(bhi_ptr);
    bhr[1] = *(const uint4*)(bhi_ptr + 4);
    blr[0] = *(const uint4*)(blo_ptr);
    blr[1] = *(const uint4*)(blo_ptr + 4);

    {
        uint32_t* buf = sm;
        uint4 hi0, hi1, lo0, lo1;
        const float* f = (const float*)ar;
        #pragma unroll
        for (int q = 0; q < 8; q++) {
            uint32_t ph, pl;
            split_pair(f[2 * q], f[2 * q + 1], ph, pl);
            if (q < 4) { ((uint32_t*)&hi0)[q] = ph; ((uint32_t*)&lo0)[q] = pl; }
            else       { ((uint32_t*)&hi1)[q - 4] = ph; ((uint32_t*)&lo1)[q - 4] = pl; }
        }
        int o = st_r * ASTR + st_kp;
        *(uint4*)(buf + OFF_AHI + o)     = hi0;
        *(uint4*)(buf + OFF_AHI + o + 4) = hi1;
        *(uint4*)(buf + OFF_ALO + o)     = lo0;
        *(uint4*)(buf + OFF_ALO + o + 4) = lo1;
        *(uint4*)(buf + OFF_BHI + o)     = bhr[0];
        *(uint4*)(buf + OFF_BHI + o + 4) = bhr[1];
        *(uint4*)(buf + OFF_BLO + o)     = blr[0];
        *(uint4*)(buf + OFF_BLO + o + 4) = blr[1];
    }
    __syncthreads();

    for (int it = 0; it < NIT; it++) {
        const int b = it & 1;
        const uint32_t bufb = sbase + b * (BUF_U32 * 4);
        const bool has_next = (it + 1) < NIT;

        if (has_next) {
            const int koff = (it + 1) * 32;
            #pragma unroll
            for (int q = 0; q < 4; q++)
                ar[q] = a_valid ? *(const float4*)(a_ptr + koff + q * 4)
                                : make_float4(0.f, 0.f, 0.f, 0.f);
            bhr[0] = *(const uint4*)(bhi_ptr + koff / 2);
            bhr[1] = *(const uint4*)(bhi_ptr + koff / 2 + 4);
            blr[0] = *(const uint4*)(blo_ptr + koff / 2);
            blr[1] = *(const uint4*)(blo_ptr + koff / 2 + 4);
        }

        #pragma unroll
        for (int ks = 0; ks < 2; ks++) {
            const int kb = ks * 8;
            uint32_t bh[4][2], bl[4][2];
            #pragma unroll
            for (int nf = 0; nf < 4; nf++) {
                int n0 = wn * 32 + nf * 8;
                uint32_t ob = (uint32_t)((n0 + lm_b_row) * ASTR + kb + lm_b_kb) * 4;
                ldsm_x2(bh[nf], bufb + OFF_BHI * 4 + ob);
                ldsm_x2(bl[nf], bufb + OFF_BLO * 4 + ob);
            }
            #pragma unroll
            for (int mf = 0; mf < 4; mf++) {
                int m0 = wm * 64 + mf * 16;
                uint32_t oa = (uint32_t)((m0 + lm_a_row) * ASTR + kb + lm_a_kb) * 4;
                uint32_t ah[4], al[4];
                ldsm_x4(ah, bufb + OFF_AHI * 4 + oa);
                ldsm_x4(al, bufb + OFF_ALO * 4 + oa);
                #pragma unroll
                for (int nf = 0; nf < 4; nf++) {
                    float* d = acc[mf][nf];
                    mma_bf16(d, ah, bh[nf]);
                    mma_bf16(d, ah, bl[nf]);
                    mma_bf16(d, al, bh[nf]);
                }
            }
        }

        if (has_next) {
            uint32_t* nbuf = sm + (b ^ 1) * BUF_U32;
            uint4 hi0, hi1, lo0, lo1;
            const float* f = (const float*)ar;
            #pragma unroll
            for (int q = 0; q < 8; q++) {
                uint32_t ph, pl;
                split_pair(f[2 * q], f[2 * q + 1], ph, pl);
                if (q < 4) { ((uint32_t*)&hi0)[q] = ph; ((uint32_t*)&lo0)[q] = pl; }
                else       { ((uint32_t*)&hi1)[q - 4] = ph; ((uint32_t*)&lo1)[q - 4] = pl; }
            }
            int o = st_r * ASTR + st_kp;
            *(uint4*)(nbuf + OFF_AHI + o)     = hi0;
            *(uint4*)(nbuf + OFF_AHI + o + 4) = hi1;
            *(uint4*)(nbuf + OFF_ALO + o)     = lo0;
            *(uint4*)(nbuf + OFF_ALO + o + 4) = lo1;
            *(uint4*)(nbuf + OFF_BHI + o)     = bhr[0];
            *(uint4*)(nbuf + OFF_BHI + o + 4) = bhr[1];
            *(uint4*)(nbuf + OFF_BLO + o)     = blr[0];
            *(uint4*)(nbuf + OFF_BLO + o + 4) = blr[1];
        }
        __syncthreads();
    }

    // ---- epilogue: raw h ----
    #pragma unroll
    for (int mf = 0; mf < 4; mf++) {
        int ra = row0 + wm * 64 + mf * 16 + gid;
        int rb = ra + 8;
        #pragma unroll
        for (int nf = 0; nf < 4; nf++) {
            int col = wn * 32 + nf * 8 + tig * 2;
            float* d = acc[mf][nf];
            if (ra < N_NODES)
                *(float2*)(g_h + (size_t)ra * HID + col) = make_float2(d[0], d[1]);
            if (rb < N_NODES)
                *(float2*)(g_h + (size_t)rb * HID + col) = make_float2(d[2], d[3]);
        }
    }
}

// ---------------- fused gather1 + gemm2: warp per dst node -----------------
// agg = dinv[d]*(dinv[d]*h[d] + sum dinv[s]*h[s]);  a = relu(agg + b1)
// g_h2[d] = (a @ W2) * dinv[d]
#define W2T_STR 132   // padded row stride (floats) -> conflict-free LDS.128

__global__ __launch_bounds__(256) void k_agg_gemm2(const float* __restrict__ W2,
                                                   const float* __restrict__ b1) {
    __shared__ float W2t[NCLS * W2T_STR];   // [c][k], padded
    __shared__ float b1s[HID];
    __shared__ float rows[8][HID];
    int tid = threadIdx.x;
    for (int i = tid; i < HID * NCLS; i += 256) {
        int k = i >> 5, c = i & 31;          // W2 is [k][c]
        W2t[c * W2T_STR + k] = W2[i];
    }
    if (tid < HID) b1s[tid] = b1[tid];
    __syncthreads();

    int w    = tid >> 5;
    int node = blockIdx.x * 8 + w;
    int lane = tid & 31;
    if (node >= N_NODES) return;

    float di = g_dinv[node];

    // self term: dinv[d]*h[d]
    float4 acc = ((const float4*)(g_h + (size_t)node * HID))[lane];
    acc.x *= di; acc.y *= di; acc.z *= di; acc.w *= di;

    int beg = g_rowptr[node], end = g_rowptr[node + 1];
    for (int i = beg; i < end; i += 32) {
        int myidx = i + lane;
        int   s  = (myidx < end) ? g_adj[myidx] : 0;
        float ds = (myidx < end) ? g_dinv[s] : 0.0f;
        int cnt = min(32, end - i);
        int j = 0;
        for (; j + 4 <= cnt; j += 4) {
            int s0 = __shfl_sync(0xFFFFFFFFu, s, j);
            int s1 = __shfl_sync(0xFFFFFFFFu, s, j + 1);
            int s2 = __shfl_sync(0xFFFFFFFFu, s, j + 2);
            int s3 = __shfl_sync(0xFFFFFFFFu, s, j + 3);
            float d0 = __shfl_sync(0xFFFFFFFFu, ds, j);
            float d1 = __shfl_sync(0xFFFFFFFFu, ds, j + 1);
            float d2 = __shfl_sync(0xFFFFFFFFu, ds, j + 2);
            float d3 = __shfl_sync(0xFFFFFFFFu, ds, j + 3);
            float4 v0 = ((const float4*)(g_h + (size_t)s0 * HID))[lane];
            float4 v1 = ((const float4*)(g_h + (size_t)s1 * HID))[lane];
            float4 v2 = ((const float4*)(g_h + (size_t)s2 * HID))[lane];
            float4 v3 = ((const float4*)(g_h + (size_t)s3 * HID))[lane];
            acc.x = fmaf(v0.x, d0, fmaf(v1.x, d1, fmaf(v2.x, d2, fmaf(v3.x, d3, acc.x))));
            acc.y = fmaf(v0.y, d0, fmaf(v1.y, d1, fmaf(v2.y, d2, fmaf(v3.y, d3, acc.y))));
            acc.z = fmaf(v0.z, d0, fmaf(v1.z, d1, fmaf(v2.z, d2, fmaf(v3.z, d3, acc.z))));
            acc.w = fmaf(v0.w, d0, fmaf(v1.w, d1, fmaf(v2.w, d2, fmaf(v3.w, d3, acc.w))));
        }
        for (; j < cnt; j++) {
            int   sj = __shfl_sync(0xFFFFFFFFu, s, j);
            float dj = __shfl_sync(0xFFFFFFFFu, ds, j);
            float4 v = ((const float4*)(g_h + (size_t)sj * HID))[lane];
            acc.x = fmaf(v.x, dj, acc.x);
            acc.y = fmaf(v.y, dj, acc.y);
            acc.z = fmaf(v.z, dj, acc.z);
            acc.w = fmaf(v.w, dj, acc.w);
        }
    }
    // a = relu(acc*di + b1), staged to smem row
    {
        const float4 bb = ((const float4*)b1s)[lane];
        float4 a;
        a.x = fmaxf(fmaf(acc.x, di, bb.x), 0.0f);
        a.y = fmaxf(fmaf(acc.y, di, bb.y), 0.0f);
        a.z = fmaxf(fmaf(acc.z, di, bb.z), 0.0f);
        a.w = fmaxf(fmaf(acc.w, di, bb.w), 0.0f);
        ((float4*)rows[w])[lane] = a;
    }
    __syncwarp();

    // ---- gemm2 phase: float4 over k, lane = out column ----
    float acc2 = 0.0f;
    const float* rw = rows[w];
    const float* wt = W2t + lane * W2T_STR;
    #pragma unroll
    for (int kq = 0; kq < HID / 4; kq++) {
        float4 av = *(const float4*)(rw + kq * 4);   // broadcast LDS.128
        float4 wv = *(const float4*)(wt + kq * 4);   // conflict-free LDS.128
        acc2 = fmaf(av.x, wv.x, acc2);
        acc2 = fmaf(av.y, wv.y, acc2);
        acc2 = fmaf(av.z, wv.z, acc2);
        acc2 = fmaf(av.w, wv.w, acc2);
    }

    g_h2[(size_t)node * NCLS + lane] = acc2 * di;
}

// ---------------- gather2: warp per dst node, 32 feats ---------------------
__global__ __launch_bounds__(256) void k_gather2(const float* __restrict__ b2,
                                                 float* __restrict__ out) {
    int node = blockIdx.x * 8 + (threadIdx.x >> 5);
    int lane = threadIdx.x & 31;
    if (node >= N_NODES) return;

    float acc = g_h2[(size_t)node * NCLS + lane];

    int beg = g_rowptr[node], end = g_rowptr[node + 1];
    for (int i = beg; i < end; i += 32) {
        int myidx = i + lane;
        int s = (myidx < end) ? g_adj[myidx] : 0;
        int cnt = min(32, end - i);
        int j = 0;
        for (; j + 4 <= cnt; j += 4) {
            int s0 = __shfl_sync(0xFFFFFFFFu, s, j);
            int s1 = __shfl_sync(0xFFFFFFFFu, s, j + 1);
            int s2 = __shfl_sync(0xFFFFFFFFu, s, j + 2);
            int s3 = __shfl_sync(0xFFFFFFFFu, s, j + 3);
            acc += g_h2[(size_t)s0 * NCLS + lane] + g_h2[(size_t)s1 * NCLS + lane]
                 + g_h2[(size_t)s2 * NCLS + lane] + g_h2[(size_t)s3 * NCLS + lane];
        }
        for (; j < cnt; j++) {
            int sj = __shfl_sync(0xFFFFFFFFu, s, j);
            acc += g_h2[(size_t)sj * NCLS + lane];
        }
    }
    out[(size_t)node * NCLS + lane] = acc * g_dinv[node] + b2[lane];
}

// ---------------- launch: CSR build forked onto a second stream ------------
extern "C" void kernel_launch(void* const* d_in, const int* in_sizes, int n_in,
                              void* d_out, int out_size) {
    const float* x  = (const float*)d_in[0];
    const int*   ei = (const int*)  d_in[1];
    const float* W1 = (const float*)d_in[2];
    const float* b1 = (const float*)d_in[3];
    const float* W2 = (const float*)d_in[4];
    const float* b2 = (const float*)d_in[5];
    float* out = (float*)d_out;

    const int E = in_sizes[1] / 2;
    const int* src = ei;
    const int* dst = ei + E;

    static cudaStream_t s2 = nullptr;
    static cudaEvent_t ev_fork = nullptr, ev_join = nullptr;
    static bool attr_set = false;
    if (!s2) {
        cudaStreamCreate(&s2);
        cudaEventCreateWithFlags(&ev_fork, cudaEventDisableTiming);
        cudaEventCreateWithFlags(&ev_join, cudaEventDisableTiming);
    }
    if (!attr_set) {
        cudaFuncSetAttribute(k_gemm1, cudaFuncAttributeMaxDynamicSharedMemorySize, SMEM_BYTES);
        attr_set = true;
    }

    // fork: CSR chain on s2, GEMM chain on the main stream
    cudaEventRecord(ev_fork, 0);
    cudaStreamWaitEvent(s2, ev_fork, 0);

    k_deg_zero  <<<(N_NODES + 255) / 256, 256, 0, s2>>>();
    k_deg_count <<<(E + 255) / 256, 256, 0, s2>>>(dst, E);
    k_scan_block<<<NB_SCAN, 1024, 0, s2>>>();
    k_scan_tops <<<1, 128, 0, s2>>>();
    k_scan_add  <<<NB_SCAN, 1024, 0, s2>>>(E);
    k_fill      <<<(E + 255) / 256, 256, 0, s2>>>(src, dst, E);
    cudaEventRecord(ev_join, s2);

    k_w1t       <<<(HID * (IN_F / 2) + 255) / 256, 256>>>(W1);
    k_gemm1     <<<(N_NODES + 127) / 128, 256, SMEM_BYTES>>>(x);

    // join
    cudaStreamWaitEvent(0, ev_join, 0);

    k_agg_gemm2 <<<(N_NODES + 7) / 8, 256>>>(W2, b1);
    k_gather2   <<<(N_NODES + 7) / 8, 256>>>(b2, out);
}

// round 16
// speedup vs baseline: 1.0941x; 1.0941x over previous
#include <cuda_runtime.h>
#include <cuda_bf16.h>
#include <cuda_fp16.h>
#include <cstdint>

#define N_NODES 100000
#define IN_F    512
#define HID     128
#define NCLS    32
#define E_MAX   1600000
#define NB_SCAN 98          // ceil(100000/1024)

// ---------------- scratch (static device globals; no allocations) ----------
__device__ __align__(16) float g_dinv[N_NODES];
__device__ __align__(16) __half g_h[(size_t)N_NODES * HID];    // raw h (x @ W1), fp16
__device__ __align__(16) float g_h2 [(size_t)N_NODES * NCLS];  // h2*dinv
// W1^T packed bf16x2: [n][kpair]
__device__ __align__(16) uint32_t g_w1t_hi[(size_t)HID * (IN_F / 2)];
__device__ __align__(16) uint32_t g_w1t_lo[(size_t)HID * (IN_F / 2)];
// CSR
__device__ int g_deg[N_NODES];
__device__ int g_rowptr[N_NODES + 1];
__device__ int g_bsums[NB_SCAN];
__device__ int g_tops[NB_SCAN];
__device__ int g_fill[N_NODES];
__device__ int g_adj[E_MAX];

// ---------------- helpers ---------------------------------------------------
__device__ __forceinline__ uint32_t smem_u32(const void* p) {
    uint32_t a;
    asm("{ .reg .u64 t; cvta.to.shared.u64 t, %1; cvt.u32.u64 %0, t; }"
        : "=r"(a) : "l"(p));
    return a;
}

__device__ __forceinline__ void ldsm_x4(uint32_t* r, uint32_t addr) {
    asm volatile("ldmatrix.sync.aligned.m8n8.x4.shared.b16 {%0,%1,%2,%3}, [%4];"
        : "=r"(r[0]), "=r"(r[1]), "=r"(r[2]), "=r"(r[3]) : "r"(addr));
}
__device__ __forceinline__ void ldsm_x2(uint32_t* r, uint32_t addr) {
    asm volatile("ldmatrix.sync.aligned.m8n8.x2.shared.b16 {%0,%1}, [%2];"
        : "=r"(r[0]), "=r"(r[1]) : "r"(addr));
}

__device__ __forceinline__ void mma_bf16(float* d, const uint32_t* a, const uint32_t* b) {
    asm volatile(
        "mma.sync.aligned.m16n8k16.row.col.f32.bf16.bf16.f32 "
        "{%0,%1,%2,%3}, {%4,%5,%6,%7}, {%8,%9}, {%0,%1,%2,%3};"
        : "+f"(d[0]), "+f"(d[1]), "+f"(d[2]), "+f"(d[3])
        : "r"(a[0]), "r"(a[1]), "r"(a[2]), "r"(a[3]), "r"(b[0]), "r"(b[1]));
}

__device__ __forceinline__ uint32_t pack_bf2(__nv_bfloat16 a, __nv_bfloat16 b) {
    return (uint32_t)__bfloat16_as_ushort(a) |
           ((uint32_t)__bfloat16_as_ushort(b) << 16);
}

// ---------------- degree / CSR build ---------------------------------------
__global__ void k_deg_zero() {
    int i = blockIdx.x * blockDim.x + threadIdx.x;
    if (i < N_NODES) g_deg[i] = 0;
}
__global__ void k_deg_count(const int* __restrict__ dst, int E) {
    int e = blockIdx.x * blockDim.x + threadIdx.x;
    if (e < E) atomicAdd(&g_deg[dst[e]], 1);
}
__global__ __launch_bounds__(1024) void k_scan_block() {
    __shared__ int s[1024];
    int tid = threadIdx.x;
    int i = blockIdx.x * 1024 + tid;
    int v = (i < N_NODES) ? g_deg[i] : 0;
    s[tid] = v;
    __syncthreads();
    #pragma unroll
    for (int off = 1; off < 1024; off <<= 1) {
        int t = (tid >= off) ? s[tid - off] : 0;
        __syncthreads();
        s[tid] += t;
        __syncthreads();
    }
    if (i < N_NODES) g_rowptr[i] = s[tid] - v;
    if (tid == 1023) g_bsums[blockIdx.x] = s[1023];
}
__global__ __launch_bounds__(128) void k_scan_tops() {
    __shared__ int s[128];
    int t = threadIdx.x;
    int v = (t < NB_SCAN) ? g_bsums[t] : 0;
    s[t] = v;
    __syncthreads();
    #pragma unroll
    for (int off = 1; off < 128; off <<= 1) {
        int u = (t >= off) ? s[t - off] : 0;
        __syncthreads();
        s[t] += u;
        __syncthreads();
    }
    if (t < NB_SCAN) g_tops[t] = s[t] - v;   // exclusive
}
__global__ __launch_bounds__(1024) void k_scan_add(int E) {
    int i = blockIdx.x * 1024 + threadIdx.x;
    if (i < N_NODES) {
        g_rowptr[i] += g_tops[blockIdx.x];
        g_fill[i] = 0;
        g_dinv[i] = rsqrtf((float)(g_deg[i] + 1));
    }
    if (i == 0) g_rowptr[N_NODES] = E;
}
__global__ void k_fill(const int* __restrict__ src, const int* __restrict__ dst, int E) {
    int e = blockIdx.x * blockDim.x + threadIdx.x;
    if (e >= E) return;
    int d = dst[e];
    int pos = atomicAdd(&g_fill[d], 1);
    g_adj[g_rowptr[d] + pos] = src[e];
}

// ---------------- W1 transpose + bf16 hi/lo split --------------------------
__global__ void k_w1t(const float* __restrict__ W1) {
    int idx = blockIdx.x * blockDim.x + threadIdx.x;
    if (idx >= HID * (IN_F / 2)) return;
    int n  = idx >> 8;
    int kp = idx & 255;
    float v0 = W1[(size_t)(2 * kp)     * HID + n];
    float v1 = W1[(size_t)(2 * kp + 1) * HID + n];
    __nv_bfloat16 h0 = __float2bfloat16_rn(v0);
    __nv_bfloat16 h1 = __float2bfloat16_rn(v1);
    __nv_bfloat16 l0 = __float2bfloat16_rn(v0 - __bfloat162float(h0));
    __nv_bfloat16 l1 = __float2bfloat16_rn(v1 - __bfloat162float(h1));
    g_w1t_hi[idx] = pack_bf2(h0, h1);
    g_w1t_lo[idx] = pack_bf2(l0, l1);
}

// ---------------- GEMM1 (bf16 mma m16n8k16, 3-term split, ldmatrix) --------
// writes RAW h (fp16) -> no dependency on CSR chain
#define ASTR 20
#define NIT  (IN_F / 32)
#define OFF_AHI 0
#define OFF_ALO 2560
#define OFF_BHI 5120
#define OFF_BLO 7680
#define BUF_U32 10240
#define SMEM_BYTES (2 * BUF_U32 * 4)   // 81920

__global__ __launch_bounds__(256, 2) void k_gemm1(const float* __restrict__ A) {
    extern __shared__ __align__(16) uint32_t sm[];
    const uint32_t sbase = smem_u32(sm);

    const int tid  = threadIdx.x;
    const int wid  = tid >> 5;
    const int lane = tid & 31;
    const int gid  = lane >> 2;
    const int tig  = lane & 3;
    const int wm   = wid >> 2;
    const int wn   = wid & 3;
    const int row0 = blockIdx.x * 128;

    const int st_r  = tid >> 1;
    const int st_kp = (tid & 1) * 8;

    const int lm_a_row = lane & 15;
    const int lm_a_kb  = ((lane >> 4) & 1) * 4;
    const int lm_b_row = lane & 7;
    const int lm_b_kb  = ((lane >> 3) & 1) * 4;

    float acc[4][4][4];
    #pragma unroll
    for (int i = 0; i < 4; i++)
        #pragma unroll
        for (int j = 0; j < 4; j++)
            #pragma unroll
            for (int v = 0; v < 4; v++) acc[i][j][v] = 0.0f;

    const bool a_valid = (row0 + st_r) < N_NODES;
    const float* a_ptr = A + (size_t)(row0 + st_r) * IN_F + st_kp * 2;
    const uint32_t* bhi_ptr = g_w1t_hi + (size_t)st_r * (IN_F / 2) + st_kp;
    const uint32_t* blo_ptr = g_w1t_lo + (size_t)st_r * (IN_F / 2) + st_kp;

    float4 ar[4];
    uint4  bhr[2], blr[2];

    #pragma unroll
    for (int q = 0; q < 4; q++)
        ar[q] = a_valid ? *(const float4*)(a_ptr + q * 4)
                        : make_float4(0.f, 0.f, 0.f, 0.f);
    bhr[0] = *(const uint4*)(bhi_ptr);
    bhr[1] = *(const uint4*)(bhi_ptr + 4);
    blr[0] = *(const uint4*)(blo_ptr);
    blr[1] = *(const uint4*)(blo_ptr + 4);

    {
        uint32_t* buf = sm;
        uint4 hi0, hi1, lo0, lo1;
        const float* f = (const float*)ar;
        #pragma unroll
        for (int q = 0; q < 8; q++) {
            float va = f[2 * q], vb = f[2 * q + 1];
            __nv_bfloat16 ha = __float2bfloat16_rn(va);
            __nv_bfloat16 hb = __float2bfloat16_rn(vb);
            uint32_t ph = pack_bf2(ha, hb);
            uint32_t pl = pack_bf2(__float2bfloat16_rn(va - __bfloat162float(ha)),
                                   __float2bfloat16_rn(vb - __bfloat162float(hb)));
            if (q < 4) { ((uint32_t*)&hi0)[q] = ph; ((uint32_t*)&lo0)[q] = pl; }
            else       { ((uint32_t*)&hi1)[q - 4] = ph; ((uint32_t*)&lo1)[q - 4] = pl; }
        }
        int o = st_r * ASTR + st_kp;
        *(uint4*)(buf + OFF_AHI + o)     = hi0;
        *(uint4*)(buf + OFF_AHI + o + 4) = hi1;
        *(uint4*)(buf + OFF_ALO + o)     = lo0;
        *(uint4*)(buf + OFF_ALO + o + 4) = lo1;
        *(uint4*)(buf + OFF_BHI + o)     = bhr[0];
        *(uint4*)(buf + OFF_BHI + o + 4) = bhr[1];
        *(uint4*)(buf + OFF_BLO + o)     = blr[0];
        *(uint4*)(buf + OFF_BLO + o + 4) = blr[1];
    }
    __syncthreads();

    for (int it = 0; it < NIT; it++) {
        const int b = it & 1;
        const uint32_t bufb = sbase + b * (BUF_U32 * 4);
        const bool has_next = (it + 1) < NIT;

        if (has_next) {
            const int koff = (it + 1) * 32;
            #pragma unroll
            for (int q = 0; q < 4; q++)
                ar[q] = a_valid ? *(const float4*)(a_ptr + koff + q * 4)
                                : make_float4(0.f, 0.f, 0.f, 0.f);
            bhr[0] = *(const uint4*)(bhi_ptr + koff / 2);
            bhr[1] = *(const uint4*)(bhi_ptr + koff / 2 + 4);
            blr[0] = *(const uint4*)(blo_ptr + koff / 2);
            blr[1] = *(const uint4*)(blo_ptr + koff / 2 + 4);
        }

        #pragma unroll
        for (int ks = 0; ks < 2; ks++) {
            const int kb = ks * 8;
            uint32_t bh[4][2], bl[4][2];
            #pragma unroll
            for (int nf = 0; nf < 4; nf++) {
                int n0 = wn * 32 + nf * 8;
                uint32_t ob = (uint32_t)((n0 + lm_b_row) * ASTR + kb + lm_b_kb) * 4;
                ldsm_x2(bh[nf], bufb + OFF_BHI * 4 + ob);
                ldsm_x2(bl[nf], bufb + OFF_BLO * 4 + ob);
            }
            #pragma unroll
            for (int mf = 0; mf < 4; mf++) {
                int m0 = wm * 64 + mf * 16;
                uint32_t oa = (uint32_t)((m0 + lm_a_row) * ASTR + kb + lm_a_kb) * 4;
                uint32_t ah[4], al[4];
                ldsm_x4(ah, bufb + OFF_AHI * 4 + oa);
                ldsm_x4(al, bufb + OFF_ALO * 4 + oa);
                #pragma unroll
                for (int nf = 0; nf < 4; nf++) {
                    float* d = acc[mf][nf];
                    mma_bf16(d, ah, bh[nf]);
                    mma_bf16(d, ah, bl[nf]);
                    mma_bf16(d, al, bh[nf]);
                }
            }
        }

        if (has_next) {
            uint32_t* nbuf = sm + (b ^ 1) * BUF_U32;
            uint4 hi0, hi1, lo0, lo1;
            const float* f = (const float*)ar;
            #pragma unroll
            for (int q = 0; q < 8; q++) {
                float va = f[2 * q], vb = f[2 * q + 1];
                __nv_bfloat16 ha = __float2bfloat16_rn(va);
                __nv_bfloat16 hb = __float2bfloat16_rn(vb);
                uint32_t ph = pack_bf2(ha, hb);
                uint32_t pl = pack_bf2(__float2bfloat16_rn(va - __bfloat162float(ha)),
                                       __float2bfloat16_rn(vb - __bfloat162float(hb)));
                if (q < 4) { ((uint32_t*)&hi0)[q] = ph; ((uint32_t*)&lo0)[q] = pl; }
                else       { ((uint32_t*)&hi1)[q - 4] = ph; ((uint32_t*)&lo1)[q - 4] = pl; }
            }
            int o = st_r * ASTR + st_kp;
            *(uint4*)(nbuf + OFF_AHI + o)     = hi0;
            *(uint4*)(nbuf + OFF_AHI + o + 4) = hi1;
            *(uint4*)(nbuf + OFF_ALO + o)     = lo0;
            *(uint4*)(nbuf + OFF_ALO + o + 4) = lo1;
            *(uint4*)(nbuf + OFF_BHI + o)     = bhr[0];
            *(uint4*)(nbuf + OFF_BHI + o + 4) = bhr[1];
            *(uint4*)(nbuf + OFF_BLO + o)     = blr[0];
            *(uint4*)(nbuf + OFF_BLO + o + 4) = blr[1];
        }
        __syncthreads();
    }

    // ---- epilogue: raw h in fp16 ----
    #pragma unroll
    for (int mf = 0; mf < 4; mf++) {
        int ra = row0 + wm * 64 + mf * 16 + gid;
        int rb = ra + 8;
        #pragma unroll
        for (int nf = 0; nf < 4; nf++) {
            int col = wn * 32 + nf * 8 + tig * 2;
            float* d = acc[mf][nf];
            if (ra < N_NODES)
                *(__half2*)(g_h + (size_t)ra * HID + col) = __floats2half2_rn(d[0], d[1]);
            if (rb < N_NODES)
                *(__half2*)(g_h + (size_t)rb * HID + col) = __floats2half2_rn(d[2], d[3]);
        }
    }
}

// ---------------- fused gather1 + gemm2: warp per dst node -----------------
// agg = dinv[d]*(dinv[d]*h[d] + sum dinv[s]*h[s]);  a = relu(agg + b1)
// g_h2[d] = (a @ W2) * dinv[d]
__device__ __forceinline__ float4 ld_h4(const __half* base, int lane) {
    uint2 u = ((const uint2*)base)[lane];
    float2 f0 = __half22float2(*(__half2*)&u.x);
    float2 f1 = __half22float2(*(__half2*)&u.y);
    return make_float4(f0.x, f0.y, f1.x, f1.y);
}

__global__ __launch_bounds__(256) void k_agg_gemm2(const float* __restrict__ W2,
                                                   const float* __restrict__ b1) {
    __shared__ float W2s[HID * NCLS];
    __shared__ float b1s[HID];
    __shared__ float rows[8][HID];
    int tid = threadIdx.x;
    for (int i = tid; i < HID * NCLS; i += 256) W2s[i] = W2[i];
    if (tid < HID) b1s[tid] = b1[tid];
    __syncthreads();

    int w    = tid >> 5;
    int node = blockIdx.x * 8 + w;
    int lane = tid & 31;
    if (node >= N_NODES) return;

    float di = g_dinv[node];

    // self term: dinv[d]*h[d]
    float4 acc = ld_h4(g_h + (size_t)node * HID, lane);
    acc.x *= di; acc.y *= di; acc.z *= di; acc.w *= di;

    int beg = g_rowptr[node], end = g_rowptr[node + 1];
    for (int i = beg; i < end; i += 32) {
        int myidx = i + lane;
        int   s  = (myidx < end) ? g_adj[myidx] : 0;
        float ds = (myidx < end) ? g_dinv[s] : 0.0f;
        int cnt = min(32, end - i);
        int j = 0;
        for (; j + 4 <= cnt; j += 4) {
            int s0 = __shfl_sync(0xFFFFFFFFu, s, j);
            int s1 = __shfl_sync(0xFFFFFFFFu, s, j + 1);
            int s2 = __shfl_sync(0xFFFFFFFFu, s, j + 2);
            int s3 = __shfl_sync(0xFFFFFFFFu, s, j + 3);
            float d0 = __shfl_sync(0xFFFFFFFFu, ds, j);
            float d1 = __shfl_sync(0xFFFFFFFFu, ds, j + 1);
            float d2 = __shfl_sync(0xFFFFFFFFu, ds, j + 2);
            float d3 = __shfl_sync(0xFFFFFFFFu, ds, j + 3);
            float4 v0 = ld_h4(g_h + (size_t)s0 * HID, lane);
            float4 v1 = ld_h4(g_h + (size_t)s1 * HID, lane);
            float4 v2 = ld_h4(g_h + (size_t)s2 * HID, lane);
            float4 v3 = ld_h4(g_h + (size_t)s3 * HID, lane);
            acc.x = fmaf(v0.x, d0, fmaf(v1.x, d1, fmaf(v2.x, d2, fmaf(v3.x, d3, acc.x))));
            acc.y = fmaf(v0.y, d0, fmaf(v1.y, d1, fmaf(v2.y, d2, fmaf(v3.y, d3, acc.y))));
            acc.z = fmaf(v0.z, d0, fmaf(v1.z, d1, fmaf(v2.z, d2, fmaf(v3.z, d3, acc.z))));
            acc.w = fmaf(v0.w, d0, fmaf(v1.w, d1, fmaf(v2.w, d2, fmaf(v3.w, d3, acc.w))));
        }
        for (; j < cnt; j++) {
            int   sj = __shfl_sync(0xFFFFFFFFu, s, j);
            float dj = __shfl_sync(0xFFFFFFFFu, ds, j);
            float4 v = ld_h4(g_h + (size_t)sj * HID, lane);
            acc.x = fmaf(v.x, dj, acc.x);
            acc.y = fmaf(v.y, dj, acc.y);
            acc.z = fmaf(v.z, dj, acc.z);
            acc.w = fmaf(v.w, dj, acc.w);
        }
    }
    // a = relu(acc*di + b1), staged to smem row
    {
        const float4 bb = ((const float4*)b1s)[lane];
        float4 a;
        a.x = fmaxf(fmaf(acc.x, di, bb.x), 0.0f);
        a.y = fmaxf(fmaf(acc.y, di, bb.y), 0.0f);
        a.z = fmaxf(fmaf(acc.z, di, bb.z), 0.0f);
        a.w = fmaxf(fmaf(acc.w, di, bb.w), 0.0f);
        ((float4*)rows[w])[lane] = a;
    }
    __syncwarp();

    // ---- gemm2 phase: out col = lane ----
    float acc2 = 0.0f;
    const float* rw = rows[w];
    #pragma unroll 16
    for (int k = 0; k < HID; k++)
        acc2 = fmaf(rw[k], W2s[k * NCLS + lane], acc2);

    g_h2[(size_t)node * NCLS + lane] = acc2 * di;
}

// ---------------- gather2: warp per dst node, 32 feats ---------------------
__global__ __launch_bounds__(256) void k_gather2(const float* __restrict__ b2,
                                                 float* __restrict__ out) {
    int node = blockIdx.x * 8 + (threadIdx.x >> 5);
    int lane = threadIdx.x & 31;
    if (node >= N_NODES) return;

    float acc = g_h2[(size_t)node * NCLS + lane];

    int beg = g_rowptr[node], end = g_rowptr[node + 1];
    for (int i = beg; i < end; i += 32) {
        int myidx = i + lane;
        int s = (myidx < end) ? g_adj[myidx] : 0;
        int cnt = min(32, end - i);
        int j = 0;
        for (; j + 4 <= cnt; j += 4) {
            int s0 = __shfl_sync(0xFFFFFFFFu, s, j);
            int s1 = __shfl_sync(0xFFFFFFFFu, s, j + 1);
            int s2 = __shfl_sync(0xFFFFFFFFu, s, j + 2);
            int s3 = __shfl_sync(0xFFFFFFFFu, s, j + 3);
            acc += g_h2[(size_t)s0 * NCLS + lane] + g_h2[(size_t)s1 * NCLS + lane]
                 + g_h2[(size_t)s2 * NCLS + lane] + g_h2[(size_t)s3 * NCLS + lane];
        }
        for (; j < cnt; j++) {
            int sj = __shfl_sync(0xFFFFFFFFu, s, j);
            acc += g_h2[(size_t)sj * NCLS + lane];
        }
    }
    out[(size_t)node * NCLS + lane] = acc * g_dinv[node] + b2[lane];
}

// ---------------- launch: CSR build forked onto a second stream ------------
extern "C" void kernel_launch(void* const* d_in, const int* in_sizes, int n_in,
                              void* d_out, int out_size) {
    const float* x  = (const float*)d_in[0];
    const int*   ei = (const int*)  d_in[1];
    const float* W1 = (const float*)d_in[2];
    const float* b1 = (const float*)d_in[3];
    const float* W2 = (const float*)d_in[4];
    const float* b2 = (const float*)d_in[5];
    float* out = (float*)d_out;

    const int E = in_sizes[1] / 2;
    const int* src = ei;
    const int* dst = ei + E;

    static cudaStream_t s2 = nullptr;
    static cudaEvent_t ev_fork = nullptr, ev_join = nullptr;
    static bool attr_set = false;
    if (!s2) {
        cudaStreamCreate(&s2);
        cudaEventCreateWithFlags(&ev_fork, cudaEventDisableTiming);
        cudaEventCreateWithFlags(&ev_join, cudaEventDisableTiming);
    }
    if (!attr_set) {
        cudaFuncSetAttribute(k_gemm1, cudaFuncAttributeMaxDynamicSharedMemorySize, SMEM_BYTES);
        attr_set = true;
    }

    // fork: CSR chain on s2, GEMM chain on the main stream
    cudaEventRecord(ev_fork, 0);
    cudaStreamWaitEvent(s2, ev_fork, 0);

    k_deg_zero  <<<(N_NODES + 255) / 256, 256, 0, s2>>>();
    k_deg_count <<<(E + 255) / 256, 256, 0, s2>>>(dst, E);
    k_scan_block<<<NB_SCAN, 1024, 0, s2>>>();
    k_scan_tops <<<1, 128, 0, s2>>>();
    k_scan_add  <<<NB_SCAN, 1024, 0, s2>>>(E);
    k_fill      <<<(E + 255) / 256, 256, 0, s2>>>(src, dst, E);
    cudaEventRecord(ev_join, s2);

    k_w1t       <<<(HID * (IN_F / 2) + 255) / 256, 256>>>(W1);
    k_gemm1     <<<(N_NODES + 127) / 128, 256, SMEM_BYTES>>>(x);

    // join
    cudaStreamWaitEvent(0, ev_join, 0);

    k_agg_gemm2 <<<(N_NODES + 7) / 8, 256>>>(W2, b1);
    k_gather2   <<<(N_NODES + 7) / 8, 256>>>(b2, out);
}